// round 1
// baseline (speedup 1.0000x reference)
#include <cuda_runtime.h>
#include <cstddef>

// Problem constants (fixed by the reference)
#define NPTS 8192
#define DIM  1024

// GEMM tiling
#define BM 128
#define BN 128
#define BK 16

// ---------------------------------------------------------------------------
// Scratch (device globals; no allocation allowed)
// ---------------------------------------------------------------------------
__device__ float g_Q[(size_t)NPTS * DIM];
__device__ float g_K[(size_t)NPTS * DIM];
__device__ float g_V[(size_t)NPTS * DIM];
__device__ float g_S[(size_t)NPTS * NPTS];      // scores, then exp(scores) in-place
__device__ float g_csum[16 * NPTS];             // partial column sums
__device__ float g_rc[NPTS];                    // 1 / column sum

// ---------------------------------------------------------------------------
// C = A @ B^T (+ bias), A:[M,K] row-major, B:[Ncols,K] row-major, C:[M,Ncols]
// 128x128 block, 256 threads, 8x8 per-thread (2x2 of 4x4 chunks)
// ---------------------------------------------------------------------------
__global__ __launch_bounds__(256) void gemm_nt_kernel(
    const float* __restrict__ A, const float* __restrict__ B,
    const float* __restrict__ bias, float* __restrict__ C,
    int M, int Ncols, int K)
{
    __shared__ float As[BK][BM + 4];
    __shared__ float Bs[BK][BN + 4];

    const int tid = threadIdx.x;
    const int tx = tid & 15;          // 0..15 -> columns
    const int ty = tid >> 4;          // 0..15 -> rows
    const size_t row0 = (size_t)blockIdx.y * BM;
    const size_t col0 = (size_t)blockIdx.x * BN;

    const int lr = tid >> 2;          // 0..63 (row within tile, +64 for 2nd half)
    const int lq = tid & 3;           // float4 index along k (BK=16 -> 4 float4)

    const float* Ap = A + (row0 + lr) * K + lq * 4;
    const float* Bp = B + (col0 + lr) * K + lq * 4;

    float acc[8][8];
#pragma unroll
    for (int i = 0; i < 8; i++)
#pragma unroll
        for (int j = 0; j < 8; j++) acc[i][j] = 0.f;

    for (int k0 = 0; k0 < K; k0 += BK) {
#pragma unroll
        for (int h = 0; h < 2; h++) {
            const int r = lr + h * 64;
            float4 av = *(const float4*)(Ap + (size_t)h * 64 * K + k0);
            As[lq * 4 + 0][r] = av.x;
            As[lq * 4 + 1][r] = av.y;
            As[lq * 4 + 2][r] = av.z;
            As[lq * 4 + 3][r] = av.w;
            float4 bv = *(const float4*)(Bp + (size_t)h * 64 * K + k0);
            Bs[lq * 4 + 0][r] = bv.x;
            Bs[lq * 4 + 1][r] = bv.y;
            Bs[lq * 4 + 2][r] = bv.z;
            Bs[lq * 4 + 3][r] = bv.w;
        }
        __syncthreads();

#pragma unroll
        for (int kk = 0; kk < BK; kk++) {
            float4 a0 = *(const float4*)&As[kk][ty * 4];
            float4 a1 = *(const float4*)&As[kk][64 + ty * 4];
            float4 b0 = *(const float4*)&Bs[kk][tx * 4];
            float4 b1 = *(const float4*)&Bs[kk][64 + tx * 4];
            float a[8] = {a0.x, a0.y, a0.z, a0.w, a1.x, a1.y, a1.z, a1.w};
            float b[8] = {b0.x, b0.y, b0.z, b0.w, b1.x, b1.y, b1.z, b1.w};
#pragma unroll
            for (int i = 0; i < 8; i++)
#pragma unroll
                for (int j = 0; j < 8; j++)
                    acc[i][j] = fmaf(a[i], b[j], acc[i][j]);
        }
        __syncthreads();
    }

#pragma unroll
    for (int i = 0; i < 8; i++) {
        const int r = (i < 4) ? (ty * 4 + i) : (64 + ty * 4 + (i - 4));
#pragma unroll
        for (int j = 0; j < 8; j++) {
            const int c = (j < 4) ? (tx * 4 + j) : (64 + tx * 4 + (j - 4));
            float v = acc[i][j];
            if (bias) v += bias[col0 + c];
            C[(row0 + r) * Ncols + col0 + c] = v;
        }
    }
}

// ---------------------------------------------------------------------------
// In-place exp + per-column partial sums (deterministic: no atomics).
// Each block handles 512 rows x 256 columns; 16 row-chunks along grid.y.
// ---------------------------------------------------------------------------
__global__ __launch_bounds__(256) void exp_colsum_kernel(
    float* __restrict__ S, float* __restrict__ csum, int M, int Ncols, int rowsPerChunk)
{
    const int j = blockIdx.x * blockDim.x + threadIdx.x;
    const int i0 = blockIdx.y * rowsPerChunk;
    float c = 0.f;
    for (int i = i0; i < i0 + rowsPerChunk; i++) {
        const size_t idx = (size_t)i * Ncols + j;
        float x = __expf(S[idx]);
        S[idx] = x;
        c += x;
    }
    csum[(size_t)blockIdx.y * Ncols + j] = c;
}

__global__ __launch_bounds__(256) void rc_kernel(
    const float* __restrict__ csum, float* __restrict__ rc, int nchunks, int Ncols)
{
    const int j = blockIdx.x * blockDim.x + threadIdx.x;
    float c = 0.f;
    for (int h = 0; h < nchunks; h++) c += csum[(size_t)h * Ncols + j];
    rc[j] = 1.0f / c;
}

// ---------------------------------------------------------------------------
// Out = P0 + E @ (diag(rc) V): E:[M,Kdim] row-major (exp(S)), V:[Kdim,Nd]
// NN GEMM; rc folded into the V (B) tile load.
// ---------------------------------------------------------------------------
__global__ __launch_bounds__(256) void gemm_pv_kernel(
    const float* __restrict__ E, const float* __restrict__ V,
    const float* __restrict__ rc, const float* __restrict__ P0,
    float* __restrict__ Out, int M, int Nd, int Kdim)
{
    __shared__ float As[BK][BM + 4];
    __shared__ float Bs[BK][BN + 4];

    const int tid = threadIdx.x;
    const int tx = tid & 15;
    const int ty = tid >> 4;
    const size_t row0 = (size_t)blockIdx.y * BM;
    const size_t col0 = (size_t)blockIdx.x * BN;

    const int lr = tid >> 2;   // A-tile row loader
    const int lq = tid & 3;

    const int bkk = tid >> 5;  // 0..7 : B-tile k row (two passes -> 16)
    const int bc4 = tid & 31;  // 0..31: float4 along 128 cols

    const float* Ap = E + (row0 + lr) * (size_t)Kdim + lq * 4;

    float acc[8][8];
#pragma unroll
    for (int i = 0; i < 8; i++)
#pragma unroll
        for (int j = 0; j < 8; j++) acc[i][j] = 0.f;

    for (int k0 = 0; k0 < Kdim; k0 += BK) {
        // A tile (transpose into As), plain copy: exp already applied in-place
#pragma unroll
        for (int h = 0; h < 2; h++) {
            const int r = lr + h * 64;
            float4 av = *(const float4*)(Ap + (size_t)h * 64 * Kdim + k0);
            As[lq * 4 + 0][r] = av.x;
            As[lq * 4 + 1][r] = av.y;
            As[lq * 4 + 2][r] = av.z;
            As[lq * 4 + 3][r] = av.w;
        }
        // B tile: V rows scaled by rc (softmax denominator)
#pragma unroll
        for (int h = 0; h < 2; h++) {
            const int kk = bkk + h * 8;
            const float s = rc[k0 + kk];
            float4 bv = *(const float4*)&V[(size_t)(k0 + kk) * Nd + col0 + bc4 * 4];
            Bs[kk][bc4 * 4 + 0] = bv.x * s;
            Bs[kk][bc4 * 4 + 1] = bv.y * s;
            Bs[kk][bc4 * 4 + 2] = bv.z * s;
            Bs[kk][bc4 * 4 + 3] = bv.w * s;
        }
        __syncthreads();

#pragma unroll
        for (int kk = 0; kk < BK; kk++) {
            float4 a0 = *(const float4*)&As[kk][ty * 4];
            float4 a1 = *(const float4*)&As[kk][64 + ty * 4];
            float4 b0 = *(const float4*)&Bs[kk][tx * 4];
            float4 b1 = *(const float4*)&Bs[kk][64 + tx * 4];
            float a[8] = {a0.x, a0.y, a0.z, a0.w, a1.x, a1.y, a1.z, a1.w};
            float b[8] = {b0.x, b0.y, b0.z, b0.w, b1.x, b1.y, b1.z, b1.w};
#pragma unroll
            for (int i = 0; i < 8; i++)
#pragma unroll
                for (int j = 0; j < 8; j++)
                    acc[i][j] = fmaf(a[i], b[j], acc[i][j]);
        }
        __syncthreads();
    }

#pragma unroll
    for (int i = 0; i < 8; i++) {
        const int r = (i < 4) ? (ty * 4 + i) : (64 + ty * 4 + (i - 4));
#pragma unroll
        for (int j = 0; j < 8; j++) {
            const int c = (j < 4) ? (tx * 4 + j) : (64 + tx * 4 + (j - 4));
            const size_t o = (row0 + r) * Nd + col0 + c;
            Out[o] = P0[o] + acc[i][j];
        }
    }
}

// ---------------------------------------------------------------------------
extern "C" void kernel_launch(void* const* d_in, const int* in_sizes, int n_in,
                              void* d_out, int out_size)
{
    const float* p  = (const float*)d_in[0];
    const float* r  = (const float*)d_in[1];
    const float* Wh = (const float*)d_in[2];
    const float* bh = (const float*)d_in[3];
    const float* Wl = (const float*)d_in[4];
    const float* bl = (const float*)d_in[5];
    const float* Wg = (const float*)d_in[6];
    const float* bg = (const float*)d_in[7];
    float* out = (float*)d_out;

    float *Q, *K, *V, *S, *csum, *rc;
    cudaGetSymbolAddress((void**)&Q, g_Q);
    cudaGetSymbolAddress((void**)&K, g_K);
    cudaGetSymbolAddress((void**)&V, g_V);
    cudaGetSymbolAddress((void**)&S, g_S);
    cudaGetSymbolAddress((void**)&csum, g_csum);
    cudaGetSymbolAddress((void**)&rc, g_rc);

    dim3 blk(256);

    // Projections: Q = p Wh^T + bh ; K = r Wl^T + bl ; V = p Wg^T + bg
    dim3 gproj(DIM / BN, NPTS / BM);
    gemm_nt_kernel<<<gproj, blk>>>(p, Wh, bh, Q, NPTS, DIM, DIM);
    gemm_nt_kernel<<<gproj, blk>>>(r, Wl, bl, K, NPTS, DIM, DIM);
    gemm_nt_kernel<<<gproj, blk>>>(p, Wg, bg, V, NPTS, DIM, DIM);

    // Scores: S = Q K^T
    dim3 gS(NPTS / BN, NPTS / BM);
    gemm_nt_kernel<<<gS, blk>>>(Q, K, nullptr, S, NPTS, NPTS, DIM);

    // Column softmax (axis 0): exp in-place + column sums (no max needed:
    // max score ~64 -> exp fits fp32 comfortably; sums < 1e32)
    dim3 gexp(NPTS / 256, 16);
    exp_colsum_kernel<<<gexp, blk>>>(S, csum, NPTS, NPTS, NPTS / 16);
    rc_kernel<<<NPTS / 256, blk>>>(csum, rc, 16, NPTS);

    // Out = p + exp(S) @ (diag(rc) V)
    dim3 gpv(DIM / BN, NPTS / BM);
    gemm_pv_kernel<<<gpv, blk>>>(S, V, rc, p, out, NPTS, DIM, NPTS);
}